// round 3
// baseline (speedup 1.0000x reference)
#include <cuda_runtime.h>

// Problem dims
#define T_TOTAL 2048
#define B_DIM   64
#define INP_DIM 512
#define OUT_DIM 512

// Tiling
#define NSEG    8           // segments over T
#define SEG_LEN (T_TOTAL / NSEG)   // 256
#define SUBT    64          // t-rows per GEMM subtile
#define NSUB    (SEG_LEN / SUBT)   // 4
#define NTILE   128         // o-columns per block
#define KSTEP   32

typedef unsigned long long ull;

// Per-segment affine maps (scratch; __device__ globals since allocation is forbidden)
__device__ float d_Aseg[NSEG * B_DIM * OUT_DIM];
__device__ float d_Bseg[NSEG * B_DIM * OUT_DIM];

// ---- packed f32x2 helpers (sm_100+) ----
__device__ __forceinline__ ull pack2(float lo, float hi) {
    ull d; asm("mov.b64 %0, {%1, %2};" : "=l"(d) : "f"(lo), "f"(hi)); return d;
}
__device__ __forceinline__ void unpack2(ull v, float& lo, float& hi) {
    asm("mov.b64 {%0, %1}, %2;" : "=f"(lo), "=f"(hi) : "l"(v));
}
__device__ __forceinline__ ull fma2(ull a, ull b, ull c) {
    ull d; asm("fma.rn.f32x2 %0, %1, %2, %3;" : "=l"(d) : "l"(a), "l"(b), "l"(c)); return d;
}
__device__ __forceinline__ ull mul2(ull a, ull b) {
    ull d; asm("mul.rn.f32x2 %0, %1, %2;" : "=l"(d) : "l"(a), "l"(b)); return d;
}

__device__ __forceinline__ float sigf(float x)  { return 1.0f / (1.0f + __expf(-x)); }
__device__ __forceinline__ float tanhf_(float x){ return 2.0f / (1.0f + __expf(-2.0f * x)) - 1.0f; }

// Fused GEMM (G and H pre-activations) + in-segment scan.
// Grid: (OUT/NTILE=4, B=64, NSEG=8). Block: 256 threads.
// Thread micro-tile: 4 t-rows x 8 o-cols (as 4 f32x2 pairs), for both G and H.
__global__ __launch_bounds__(256, 2)
void rnn_seg_kernel(const float* __restrict__ x,  const float* __restrict__ g,
                    const float* __restrict__ gb, const float* __restrict__ h,
                    const float* __restrict__ hb, const float* __restrict__ r,
                    const float* __restrict__ rb)
{
    __shared__ float xs[SUBT][36];       // [t][k] slice, padded rows
    __shared__ ull   wgs[KSTEP][66];     // [k][o-pair] packed g weights, padded
    __shared__ ull   whs[KSTEP][66];     // [k][o-pair] packed h weights
    __shared__ ull   stateA[NTILE / 2];  // running segment affine map (per o-pair)
    __shared__ ull   stateB[NTILE / 2];

    // span scratch aliases the weight tiles (weights are restaged every k-step,
    // spans are only live between the k-loop end and the next staging; syncs separate)
    ull (*spanA)[NTILE / 2] = reinterpret_cast<ull (*)[NTILE / 2]>(&wgs[0][0]); // [16][64]
    ull (*spanB)[NTILE / 2] = reinterpret_cast<ull (*)[NTILE / 2]>(&whs[0][0]);

    const int tid = threadIdx.x;
    const int og  = tid & 15;   // o-group (8 o's = 4 pairs)
    const int tg  = tid >> 4;   // t-group (4 consecutive t rows)
    const int s   = blockIdx.z;
    const int b   = blockIdx.y;
    const int o0  = blockIdx.x * NTILE;

    if (tid < NTILE / 2) {
        stateA[tid] = pack2(1.0f, 1.0f);
        stateB[tid] = 0ull;  // (0.0f, 0.0f)
    }

    for (int sub = 0; sub < NSUB; sub++) {
        const int t0 = s * SEG_LEN + sub * SUBT;

        ull accG[4][4];
        ull accH[4][4];
        #pragma unroll
        for (int i = 0; i < 4; i++)
            #pragma unroll
            for (int j = 0; j < 4; j++) { accG[i][j] = 0ull; accH[i][j] = 0ull; }

        for (int kk = 0; kk < INP_DIM / KSTEP; kk++) {
            const int k0 = kk * KSTEP;
            __syncthreads();   // protect smem from previous consumers

            // ---- stage x slice [64t x 32k] ----
            #pragma unroll
            for (int q8 = 0; q8 < 2; q8++) {
                int q  = tid + 256 * q8;          // 0..511 float4 chunks
                int tt = q >> 3;
                int kq = (q & 7) * 4;
                float4 v = *(const float4*)&x[((size_t)(t0 + tt) * B_DIM + b) * INP_DIM + k0 + kq];
                *(float4*)&xs[tt][kq] = v;
            }
            // ---- stage weight tiles [32k x 128o] for g and h (packed o-pairs) ----
            #pragma unroll
            for (int q4 = 0; q4 < 4; q4++) {
                int q  = tid + 256 * q4;          // 0..1023 float4 chunks
                int kr = q >> 5;
                int oq = (q & 31) * 4;
                float4 vg = *(const float4*)&g[(size_t)(k0 + kr) * OUT_DIM + o0 + oq];
                *(float4*)&wgs[kr][oq >> 1] = vg;
                float4 vh = *(const float4*)&h[(size_t)(k0 + kr) * OUT_DIM + o0 + oq];
                *(float4*)&whs[kr][oq >> 1] = vh;
            }
            __syncthreads();

            // ---- GEMM micro-kernel over this k-slice ----
            #pragma unroll 4
            for (int k = 0; k < KSTEP; k++) {
                ull xx[4];
                #pragma unroll
                for (int i = 0; i < 4; i++) {
                    float xv = xs[tg * 4 + i][k];
                    xx[i] = pack2(xv, xv);
                }
                ull wgv[4], whv[4];
                #pragma unroll
                for (int j = 0; j < 4; j++) {
                    wgv[j] = wgs[k][og * 4 + j];
                    whv[j] = whs[k][og * 4 + j];
                }
                #pragma unroll
                for (int i = 0; i < 4; i++)
                    #pragma unroll
                    for (int j = 0; j < 4; j++) {
                        accG[i][j] = fma2(xx[i], wgv[j], accG[i][j]);
                        accH[i][j] = fma2(xx[i], whv[j], accH[i][j]);
                    }
            }
        }

        __syncthreads();  // done reading wgs/whs; spans may now overwrite them

        // ---- epilogue: activations + per-thread 4-step span compose ----
        #pragma unroll
        for (int j = 0; j < 4; j++) {
            const int o = o0 + (og * 4 + j) * 2;
            const float gb0 = gb[o], gb1 = gb[o + 1];
            const float hb0 = hb[o], hb1 = hb[o + 1];
            const float r0  = r[o],  r1  = r[o + 1];
            const float rb0 = rb[o], rb1 = rb[o + 1];
            ull Aj = pack2(1.0f, 1.0f);
            ull Bj = 0ull;
            #pragma unroll
            for (int i = 0; i < 4; i++) {
                const int   t  = t0 + tg * 4 + i;
                const float tn = (float)t * (1.0f / (float)T_TOTAL);
                float a0, a1, c0, c1;
                unpack2(accG[i][j], a0, a1);
                unpack2(accH[i][j], c0, c1);
                const float rt0 = 2.0f * sigf(fmaf(tn, r0, rb0));
                const float rt1 = 2.0f * sigf(fmaf(tn, r1, rb1));
                const float G0 = sigf(a0 + gb0) * rt0;
                const float G1 = sigf(a1 + gb1) * rt1;
                const float H0 = tanhf_(c0 + hb0) * rt0;
                const float H1 = tanhf_(c1 + hb1) * rt1;
                const ull G2 = pack2(G0, G1);
                const ull H2 = pack2(H0, H1);
                Bj = fma2(Bj, G2, H2);   // B <- B*G + H
                Aj = mul2(Aj, G2);       // A <- A*G
            }
            spanA[tg][og * 4 + j] = Aj;
            spanB[tg][og * 4 + j] = Bj;
        }
        __syncthreads();

        // ---- compose the 16 spans in t-order into the running segment state ----
        if (tid < NTILE / 2) {
            ull Ar = stateA[tid], Br = stateB[tid];
            #pragma unroll
            for (int tgi = 0; tgi < 16; tgi++) {
                ull a  = spanA[tgi][tid];
                ull bb = spanB[tgi][tid];
                Br = fma2(Br, a, bb);    // B <- B*a + b
                Ar = mul2(Ar, a);        // A <- A*a
            }
            stateA[tid] = Ar;
            stateB[tid] = Br;
        }
        __syncthreads();
    }

    // ---- write per-segment affine map ----
    if (tid < NTILE / 2) {
        size_t idx = ((size_t)s * B_DIM + b) * OUT_DIM + o0 + tid * 2;
        *(ull*)&d_Aseg[idx] = stateA[tid];
        *(ull*)&d_Bseg[idx] = stateB[tid];
    }
}

// Fold the NSEG segment maps in order: y <- y*A_s + B_s, y0 = 0
__global__ void rnn_combine_kernel(float* __restrict__ out)
{
    const int idx = blockIdx.x * blockDim.x + threadIdx.x;  // (b*OUT + o)
    float y = 0.0f;
    #pragma unroll
    for (int s = 0; s < NSEG; s++) {
        float A = d_Aseg[s * B_DIM * OUT_DIM + idx];
        float B = d_Bseg[s * B_DIM * OUT_DIM + idx];
        y = fmaf(y, A, B);
    }
    out[idx] = y;
}

extern "C" void kernel_launch(void* const* d_in, const int* in_sizes, int n_in,
                              void* d_out, int out_size)
{
    const float* x  = (const float*)d_in[0];
    const float* g  = (const float*)d_in[1];
    const float* gb = (const float*)d_in[2];
    const float* h  = (const float*)d_in[3];
    const float* hb = (const float*)d_in[4];
    const float* r  = (const float*)d_in[5];
    const float* rb = (const float*)d_in[6];
    float* out = (float*)d_out;

    dim3 grid(OUT_DIM / NTILE, B_DIM, NSEG);  // (4, 64, 8)
    rnn_seg_kernel<<<grid, 256>>>(x, g, gb, h, hb, r, rb);
    rnn_combine_kernel<<<(B_DIM * OUT_DIM) / 512, 512>>>(out);
}

// round 7
// speedup vs baseline: 2.4813x; 2.4813x over previous
#include <cuda_runtime.h>
#include <cuda_bf16.h>
#include <cstdint>

#define T_TOTAL 2048
#define B_DIM   64
#define INP_DIM 512
#define OUT_DIM 512

#define NSEG    8
#define SEG_LEN 256            // T per segment
#define MTILE   64             // t rows per block tile
#define NSUB    (SEG_LEN / MTILE)   // 4
#define OTILE   128            // o cols per block
#define KBLK    64             // K per staged slice
#define NKBLK   (INP_DIM / KBLK)    // 8

typedef unsigned long long ull;
typedef unsigned int u32;

// ---- device scratch (no allocation allowed) ----
__device__ float d_Aseg[NSEG * B_DIM * OUT_DIM];
__device__ float d_Bseg[NSEG * B_DIM * OUT_DIM];
// transposed + split weights: [o][k] bf16
__device__ __nv_bfloat16 d_wgh[OUT_DIM * INP_DIM];
__device__ __nv_bfloat16 d_wgl[OUT_DIM * INP_DIM];
__device__ __nv_bfloat16 d_whh[OUT_DIM * INP_DIM];
__device__ __nv_bfloat16 d_whl[OUT_DIM * INP_DIM];

// ---- smem layout (bytes) ----
#define SOFF_BIAS 0                     // gb[128],hb[128],r[128],rb[128] floats = 2048
#define SOFF_QA   2048                  // [4][128] floats
#define SOFF_QB   4096
#define SOFF_STA  6144                  // [128] floats
#define SOFF_STB  6656
#define SOFF_XH   8192                  // 64t x 64k bf16 = 8KB (SW128)
#define SOFF_XL   16384
#define SOFF_WGH  24576                 // 128o x 64k bf16 = 16KB each
#define SOFF_WGL  40960
#define SOFF_WHH  57344
#define SOFF_WHL  73728
#define SOFF_GA   24576                 // alias: [64][128] float = 32KB (G gate)
#define SOFF_GB   57344                 // alias: [64][128] float = 32KB (H gate)
#define SMEM_BYTES 90112

// ---- helpers ----
__device__ __forceinline__ u32 smem_u32(const void* p) {
    u32 a;
    asm("{ .reg .u64 t; cvta.to.shared.u64 t, %1; cvt.u32.u64 %0, t; }" : "=r"(a) : "l"(p));
    return a;
}
__device__ __forceinline__ void ldsm_x4(u32* r, u32 addr) {
    asm volatile("ldmatrix.sync.aligned.m8n8.x4.shared.b16 {%0,%1,%2,%3}, [%4];"
        : "=r"(r[0]), "=r"(r[1]), "=r"(r[2]), "=r"(r[3]) : "r"(addr));
}
__device__ __forceinline__ void ldsm_x2(u32* r, u32 addr) {
    asm volatile("ldmatrix.sync.aligned.m8n8.x2.shared.b16 {%0,%1}, [%2];"
        : "=r"(r[0]), "=r"(r[1]) : "r"(addr));
}
__device__ __forceinline__ void mma16816(float* d, const u32* a, const u32* b) {
    asm volatile("mma.sync.aligned.m16n8k16.row.col.f32.bf16.bf16.f32 "
                 "{%0,%1,%2,%3}, {%4,%5,%6,%7}, {%8,%9}, {%0,%1,%2,%3};"
        : "+f"(d[0]), "+f"(d[1]), "+f"(d[2]), "+f"(d[3])
        : "r"(a[0]), "r"(a[1]), "r"(a[2]), "r"(a[3]), "r"(b[0]), "r"(b[1]));
}
__device__ __forceinline__ float sigf(float x)  { return 1.0f / (1.0f + __expf(-x)); }
__device__ __forceinline__ float tanhf_(float x){ return 2.0f / (1.0f + __expf(-2.0f * x)) - 1.0f; }
__device__ __forceinline__ ull pack4(__nv_bfloat16 a, __nv_bfloat16 b, __nv_bfloat16 c, __nv_bfloat16 d) {
    return (ull)__bfloat16_as_ushort(a) | ((ull)__bfloat16_as_ushort(b) << 16)
         | ((ull)__bfloat16_as_ushort(c) << 32) | ((ull)__bfloat16_as_ushort(d) << 48);
}

// ---------------- weight prep: transpose + bf16 hi/lo split ----------------
__global__ void wprep_kernel(const float* __restrict__ g, const float* __restrict__ h)
{
    int idx = blockIdx.x * 256 + threadIdx.x;        // over 512*512, k-major in
    int k = idx >> 9, o = idx & 511;
    int oidx = o * INP_DIM + k;
    float vg = g[idx];
    __nv_bfloat16 gh = __float2bfloat16(vg);
    d_wgh[oidx] = gh;
    d_wgl[oidx] = __float2bfloat16(vg - __bfloat162float(gh));
    float vh = h[idx];
    __nv_bfloat16 hh = __float2bfloat16(vh);
    d_whh[oidx] = hh;
    d_whl[oidx] = __float2bfloat16(vh - __bfloat162float(hh));
}

// ---------------- main fused kernel ----------------
// Grid: (OUT/OTILE=4, B=64, NSEG=8) = 2048 blocks, 512 threads (16 warps).
// Warp w: gate = w>>3 (0:G, 1:H), tq = (w>>2)&1 (32-t chunk), oq = w&3 (32-o chunk).
// Per-warp tile: 32t x 32o, one gate. mma m16n8k16, 3-term bf16 split.
__global__ __launch_bounds__(512)
void rnn_mma_kernel(const float* __restrict__ x,
                    const float* __restrict__ gb, const float* __restrict__ hb,
                    const float* __restrict__ r,  const float* __restrict__ rb)
{
    extern __shared__ char smem[];
    const u32 sb   = smem_u32(smem);
    const int tid  = threadIdx.x;
    const int lane = tid & 31;
    const int w    = tid >> 5;
    const int oq   = w & 3;
    const int tq   = (w >> 2) & 1;
    const int gate = w >> 3;
    const int s    = blockIdx.z;
    const int b    = blockIdx.y;
    const int o0   = blockIdx.x * OTILE;

    float* biasG  = (float*)(smem + SOFF_BIAS);
    float* biasH  = biasG + 128;
    float* biasR  = biasG + 256;
    float* biasRB = biasG + 384;
    float* qA     = (float*)(smem + SOFF_QA);
    float* qB     = (float*)(smem + SOFF_QB);
    float* stateA = (float*)(smem + SOFF_STA);
    float* stateB = (float*)(smem + SOFF_STB);

    if (tid < 128) {
        biasG[tid]  = gb[o0 + tid];
        biasH[tid]  = hb[o0 + tid];
        biasR[tid]  = r [o0 + tid];
        biasRB[tid] = rb[o0 + tid];
        stateA[tid] = 1.0f;
        stateB[tid] = 0.0f;
    }

    // ldmatrix per-lane address bases
    const int rowA  = tq * 32 + (lane & 15);             // t row within xs (plus mt*16)
    const u32 aXor  = ((u32)(rowA & 7)) << 4;            // (row&7 invariant under +16)
    const u32 aC0   = ((u32)(lane >> 4)) << 4;           // 0 or 16 bytes
    const u32 aBaseH = sb + SOFF_XH + (u32)rowA * 128;
    const u32 aBaseL = sb + SOFF_XL + (u32)rowA * 128;

    const int rowB0 = oq * 32 + (lane & 7);              // o row (plus nt*8)
    const u32 bC0   = ((u32)((lane >> 3) & 1)) << 4;
    const u32 whBase = sb + (gate ? SOFF_WHH : SOFF_WGH);
    const u32 wlBase = sb + (gate ? SOFF_WHL : SOFF_WGL);

    for (int sub = 0; sub < NSUB; sub++) {
        const int t0 = s * SEG_LEN + sub * MTILE;

        float acc[2][4][4];
        #pragma unroll
        for (int mt = 0; mt < 2; mt++)
            #pragma unroll
            for (int nt = 0; nt < 4; nt++)
                #pragma unroll
                for (int e = 0; e < 4; e++) acc[mt][nt][e] = 0.0f;

        for (int kb = 0; kb < NKBLK; kb++) {
            const int k0 = kb * KBLK;
            __syncthreads();   // previous consumers of smem done

            // ---- stage x: 64t x 64k fp32 -> bf16 hi/lo, SW128 swizzled ----
            #pragma unroll
            for (int it = 0; it < 2; it++) {
                int q  = tid + 512 * it;          // 0..1023 float4 chunks
                int m  = q >> 4;
                int f4 = q & 15;
                const float4 v = *(const float4*)&x[((size_t)(t0 + m) * B_DIM + b) * INP_DIM + k0 + f4 * 4];
                __nv_bfloat16 h0 = __float2bfloat16(v.x), h1 = __float2bfloat16(v.y),
                              h2 = __float2bfloat16(v.z), h3 = __float2bfloat16(v.w);
                ull hi = pack4(h0, h1, h2, h3);
                ull lo = pack4(__float2bfloat16(v.x - __bfloat162float(h0)),
                               __float2bfloat16(v.y - __bfloat162float(h1)),
                               __float2bfloat16(v.z - __bfloat162float(h2)),
                               __float2bfloat16(v.w - __bfloat162float(h3)));
                u32 off = (u32)m * 128 + (u32)f4 * 8;
                u32 sw  = off ^ (((u32)(m & 7)) << 4);
                *(ull*)(smem + SOFF_XH + sw) = hi;
                *(ull*)(smem + SOFF_XL + sw) = lo;
            }
            // ---- stage weight tiles: 128o x 64k bf16, SW128 swizzled ----
            {
                const __nv_bfloat16* wp[4] = { d_wgh, d_wgl, d_whh, d_whl };
                const u32 so[4] = { SOFF_WGH, SOFF_WGL, SOFF_WHH, SOFF_WHL };
                #pragma unroll
                for (int a = 0; a < 4; a++) {
                    #pragma unroll
                    for (int it = 0; it < 2; it++) {
                        int q   = tid + 512 * it;    // 0..1023 uint4 chunks
                        int row = q >> 3;
                        int u4  = q & 7;
                        uint4 v = *(const uint4*)&wp[a][(size_t)(o0 + row) * INP_DIM + k0 + u4 * 8];
                        u32 off = (u32)row * 128 + (u32)u4 * 16;
                        *(uint4*)(smem + so[a] + (off ^ (((u32)(row & 7)) << 4))) = v;
                    }
                }
            }
            __syncthreads();

            // ---- compute: 4 k16 steps ----
            #pragma unroll
            for (int ks = 0; ks < 4; ks++) {
                u32 ah[2][4], al[2][4];
                #pragma unroll
                for (int mt = 0; mt < 2; mt++) {
                    u32 c = (aC0 + (u32)ks * 32) ^ aXor;
                    ldsm_x4(ah[mt], aBaseH + (u32)mt * 2048 + c);
                    ldsm_x4(al[mt], aBaseL + (u32)mt * 2048 + c);
                }
                #pragma unroll
                for (int nt = 0; nt < 4; nt++) {
                    const int rowB = rowB0 + nt * 8;
                    const u32 boff = (u32)rowB * 128 + ((bC0 + (u32)ks * 32) ^ (((u32)(rowB & 7)) << 4));
                    u32 bh[2], bl[2];
                    ldsm_x2(bh, whBase + boff);
                    ldsm_x2(bl, wlBase + boff);
                    #pragma unroll
                    for (int mt = 0; mt < 2; mt++) {
                        mma16816(acc[mt][nt], ah[mt], bh);
                        mma16816(acc[mt][nt], ah[mt], bl);
                        mma16816(acc[mt][nt], al[mt], bh);
                    }
                }
            }
        }
        __syncthreads();   // all mma smem reads done; GA/GB may alias weights now

        // ---- epilogue: activations at mma layout -> smem [64t][128o] ----
        {
            float* dst = (float*)(smem + (gate ? SOFF_GB : SOFF_GA));
            #pragma unroll
            for (int mt = 0; mt < 2; mt++)
                #pragma unroll
                for (int nt = 0; nt < 4; nt++)
                    #pragma unroll
                    for (int e = 0; e < 4; e++) {
                        const int tl = tq * 32 + mt * 16 + (lane >> 2) + ((e >> 1) * 8);
                        const int oo = oq * 32 + nt * 8 + (lane & 3) * 2 + (e & 1);
                        const float tn = (float)(t0 + tl) * (1.0f / (float)T_TOTAL);
                        const float rt = 2.0f * sigf(fmaf(tn, biasR[oo], biasRB[oo]));
                        const float v  = acc[mt][nt][e];
                        dst[tl * 128 + oo] = gate ? (tanhf_(v + biasH[oo]) * rt)
                                                  : (sigf (v + biasG[oo]) * rt);
                    }
        }
        __syncthreads();

        // ---- scan: 4 quarter-spans of 16 t each, per o ----
        {
            const int oo = tid & 127, qt = tid >> 7;
            const float* GA = (const float*)(smem + SOFF_GA);
            const float* GB = (const float*)(smem + SOFF_GB);
            float A = 1.0f, Bv = 0.0f;
            #pragma unroll
            for (int i = 0; i < 16; i++) {
                const int tl = qt * 16 + i;
                const float a  = GA[tl * 128 + oo];
                const float bb = GB[tl * 128 + oo];
                Bv = fmaf(Bv, a, bb);
                A *= a;
            }
            qA[qt * 128 + oo] = A;
            qB[qt * 128 + oo] = Bv;
        }
        __syncthreads();

        if (tid < 128) {
            float As = stateA[tid], Bs = stateB[tid];
            #pragma unroll
            for (int qt = 0; qt < 4; qt++) {
                const float a  = qA[qt * 128 + tid];
                const float bb = qB[qt * 128 + tid];
                Bs = fmaf(Bs, a, bb);
                As *= a;
            }
            stateA[tid] = As;
            stateB[tid] = Bs;
        }
        // next loop's kb-top __syncthreads() orders this vs restaging
    }

    __syncthreads();
    if (tid < 128) {
        const size_t idx = ((size_t)s * B_DIM + b) * OUT_DIM + o0 + tid;
        d_Aseg[idx] = stateA[tid];
        d_Bseg[idx] = stateB[tid];
    }
}

// ---------------- final combine over segments ----------------
__global__ void rnn_combine_kernel(float* __restrict__ out)
{
    const int idx = blockIdx.x * blockDim.x + threadIdx.x;
    float y = 0.0f;
    #pragma unroll
    for (int s = 0; s < NSEG; s++) {
        const float A = d_Aseg[s * B_DIM * OUT_DIM + idx];
        const float B = d_Bseg[s * B_DIM * OUT_DIM + idx];
        y = fmaf(y, A, B);
    }
    out[idx] = y;
}

extern "C" void kernel_launch(void* const* d_in, const int* in_sizes, int n_in,
                              void* d_out, int out_size)
{
    const float* x  = (const float*)d_in[0];
    const float* g  = (const float*)d_in[1];
    const float* gb = (const float*)d_in[2];
    const float* h  = (const float*)d_in[3];
    const float* hb = (const float*)d_in[4];
    const float* r  = (const float*)d_in[5];
    const float* rb = (const float*)d_in[6];
    float* out = (float*)d_out;

    cudaFuncSetAttribute(rnn_mma_kernel, cudaFuncAttributeMaxDynamicSharedMemorySize, SMEM_BYTES);

    wprep_kernel<<<(OUT_DIM * INP_DIM) / 256, 256>>>(g, h);
    dim3 grid(OUT_DIM / OTILE, B_DIM, NSEG);   // (4, 64, 8)
    rnn_mma_kernel<<<grid, 512, SMEM_BYTES>>>(x, gb, hb, r, rb);
    rnn_combine_kernel<<<(B_DIM * OUT_DIM) / 512, 512>>>(out);
}

// round 8
// speedup vs baseline: 4.2631x; 1.7181x over previous
#include <cuda_runtime.h>
#include <cuda_fp16.h>
#include <cstdint>

#define T_TOTAL 2048
#define B_DIM   64
#define INP_DIM 512
#define OUT_DIM 512

#define NSEG    8
#define SEG_LEN 256            // T per segment
#define MTILE   64             // t rows per block tile
#define NSUB    (SEG_LEN / MTILE)   // 4
#define OTILE   128            // o cols per block
#define KBLK    64             // K per staged slice
#define NKBLK   (INP_DIM / KBLK)    // 8

typedef unsigned long long ull;
typedef unsigned int u32;

// ---- device scratch ----
__device__ float d_Aseg[NSEG * B_DIM * OUT_DIM];
__device__ float d_Bseg[NSEG * B_DIM * OUT_DIM];
// transposed fp16 weights: [o][k]
__device__ __half d_wg[OUT_DIM * INP_DIM];
__device__ __half d_wh[OUT_DIM * INP_DIM];

// ---- smem layout (bytes) ----
#define SOFF_BIAS 0                     // gb,hb,r,rb floats [4][128] = 2048
#define SOFF_QA   2048                  // [4][128] floats
#define SOFF_QB   4096
#define SOFF_STA  6144                  // [128] floats
#define SOFF_STB  6656
#define SOFF_BUF0 8192                  // two 40KB staging buffers
#define BUF_X     0                     // 64t x 64k fp16 = 8KB (SW128)
#define BUF_WG    8192                  // 128o x 64k fp16 = 16KB
#define BUF_WH    24576                 // 16KB
#define BUF_BYTES 40960
#define SOFF_GA   8192                  // alias: [64][128] float = 32KB
#define SOFF_GB   40960                 // alias: [64][128] float = 32KB
#define SMEM_BYTES (SOFF_BUF0 + 2 * BUF_BYTES)   // 90112

// ---- helpers ----
__device__ __forceinline__ u32 smem_u32(const void* p) {
    u32 a;
    asm("{ .reg .u64 t; cvta.to.shared.u64 t, %1; cvt.u32.u64 %0, t; }" : "=r"(a) : "l"(p));
    return a;
}
__device__ __forceinline__ void ldsm_x4(u32* r, u32 addr) {
    asm volatile("ldmatrix.sync.aligned.m8n8.x4.shared.b16 {%0,%1,%2,%3}, [%4];"
        : "=r"(r[0]), "=r"(r[1]), "=r"(r[2]), "=r"(r[3]) : "r"(addr));
}
__device__ __forceinline__ void ldsm_x2(u32* r, u32 addr) {
    asm volatile("ldmatrix.sync.aligned.m8n8.x2.shared.b16 {%0,%1}, [%2];"
        : "=r"(r[0]), "=r"(r[1]) : "r"(addr));
}
__device__ __forceinline__ void mma16816(float* d, const u32* a, const u32* b) {
    asm volatile("mma.sync.aligned.m16n8k16.row.col.f32.f16.f16.f32 "
                 "{%0,%1,%2,%3}, {%4,%5,%6,%7}, {%8,%9}, {%0,%1,%2,%3};"
        : "+f"(d[0]), "+f"(d[1]), "+f"(d[2]), "+f"(d[3])
        : "r"(a[0]), "r"(a[1]), "r"(a[2]), "r"(a[3]), "r"(b[0]), "r"(b[1]));
}
__device__ __forceinline__ void cp_async16(u32 saddr, const void* gaddr) {
    asm volatile("cp.async.cg.shared.global [%0], [%1], 16;" :: "r"(saddr), "l"(gaddr));
}
#define CP_COMMIT()  asm volatile("cp.async.commit_group;" ::: "memory")
#define CP_WAIT(n)   asm volatile("cp.async.wait_group %0;" :: "n"(n) : "memory")

__device__ __forceinline__ float sigf(float x)  { return 1.0f / (1.0f + __expf(-x)); }
__device__ __forceinline__ float tanhf_(float x){ return 2.0f / (1.0f + __expf(-2.0f * x)) - 1.0f; }

// ---------------- weight prep: tiled transpose fp32[k][o] -> fp16[o][k] ----------------
__global__ void wprep_kernel(const float* __restrict__ g, const float* __restrict__ h)
{
    __shared__ float tg[32][33], th[32][33];
    const int k0 = blockIdx.y * 32, o0 = blockIdx.x * 32;
    const int tx = threadIdx.x, ty = threadIdx.y;
    tg[ty][tx] = g[(size_t)(k0 + ty) * OUT_DIM + o0 + tx];
    th[ty][tx] = h[(size_t)(k0 + ty) * OUT_DIM + o0 + tx];
    __syncthreads();
    d_wg[(size_t)(o0 + ty) * INP_DIM + k0 + tx] = __float2half_rn(tg[tx][ty]);
    d_wh[(size_t)(o0 + ty) * INP_DIM + k0 + tx] = __float2half_rn(th[tx][ty]);
}

// ---------------- main fused kernel ----------------
// Grid: (4, 64, 8) = 2048 blocks, 512 threads (16 warps).
// Warp w: gate = w>>3 (0:G, 1:H), tq = (w>>2)&1 (32-t chunk), oq = w&3 (32-o chunk).
// Per-warp tile: 32t x 32o, one gate, single fp16 mma m16n8k16.
__global__ __launch_bounds__(512)
void rnn_mma_kernel(const float* __restrict__ x,
                    const float* __restrict__ gb, const float* __restrict__ hb,
                    const float* __restrict__ r,  const float* __restrict__ rb)
{
    extern __shared__ char smem[];
    const u32 sb   = smem_u32(smem);
    const int tid  = threadIdx.x;
    const int lane = tid & 31;
    const int w    = tid >> 5;
    const int oq   = w & 3;
    const int tq   = (w >> 2) & 1;
    const int gate = w >> 3;
    const int s    = blockIdx.z;
    const int b    = blockIdx.y;
    const int o0   = blockIdx.x * OTILE;

    float* biasG  = (float*)(smem + SOFF_BIAS);
    float* biasH  = biasG + 128;
    float* biasR  = biasG + 256;
    float* biasRB = biasG + 384;
    float* qA     = (float*)(smem + SOFF_QA);
    float* qB     = (float*)(smem + SOFF_QB);
    float* stateA = (float*)(smem + SOFF_STA);
    float* stateB = (float*)(smem + SOFF_STB);

    if (tid < 128) {
        biasG[tid]  = gb[o0 + tid];
        biasH[tid]  = hb[o0 + tid];
        biasR[tid]  = r [o0 + tid];
        biasRB[tid] = rb[o0 + tid];
        stateA[tid] = 1.0f;
        stateB[tid] = 0.0f;
    }

    // ---- staging helper (captured as lambda for double buffering) ----
    // x: thread handles 2 float4 chunks (64t x 64k). weights: cp.async 16B x2 per array.
    auto stage = [&](u32 bufoff, int t0, int k0) {
        // x fp32 -> fp16, SW128 swizzled
        #pragma unroll
        for (int it = 0; it < 2; it++) {
            int q  = tid + 512 * it;          // 0..1023 float4 chunks
            int m  = q >> 4;
            int f4 = q & 15;
            const float4 v = *(const float4*)&x[((size_t)(t0 + m) * B_DIM + b) * INP_DIM + k0 + f4 * 4];
            __half2 p0 = __floats2half2_rn(v.x, v.y);
            __half2 p1 = __floats2half2_rn(v.z, v.w);
            u32 off = (u32)m * 128 + (u32)f4 * 8;
            u32 sw  = off ^ (((u32)(m & 7)) << 4);
            ull d = (ull)*(u32*)&p0 | ((ull)*(u32*)&p1 << 32);
            *(ull*)(smem + bufoff + BUF_X + sw) = d;
        }
        // weights via cp.async (no conversion, no regs)
        #pragma unroll
        for (int it = 0; it < 2; it++) {
            int q   = tid + 512 * it;         // 0..1023 16B chunks per array
            int row = q >> 3;
            int u4  = q & 7;
            u32 off = (u32)row * 128 + (u32)u4 * 16;
            u32 sw  = off ^ (((u32)(row & 7)) << 4);
            cp_async16(sb + bufoff + BUF_WG + sw, &d_wg[(size_t)(o0 + row) * INP_DIM + k0 + u4 * 8]);
            cp_async16(sb + bufoff + BUF_WH + sw, &d_wh[(size_t)(o0 + row) * INP_DIM + k0 + u4 * 8]);
        }
        CP_COMMIT();
    };

    // ldmatrix per-lane address pieces
    const int rowA  = tq * 32 + (lane & 15);
    const u32 aXor  = ((u32)(rowA & 7)) << 4;
    const u32 aC0   = ((u32)(lane >> 4)) << 4;
    const int rowB0 = oq * 32 + (lane & 7);
    const u32 bC0   = ((u32)((lane >> 3) & 1)) << 4;
    const u32 wSel  = gate ? BUF_WH : BUF_WG;

    for (int sub = 0; sub < NSUB; sub++) {
        const int t0 = s * SEG_LEN + sub * MTILE;

        float acc[2][4][4];
        #pragma unroll
        for (int mt = 0; mt < 2; mt++)
            #pragma unroll
            for (int nt = 0; nt < 4; nt++)
                #pragma unroll
                for (int e = 0; e < 4; e++) acc[mt][nt][e] = 0.0f;

        __syncthreads();                 // prior consumers of buffer smem done
        stage(SOFF_BUF0, t0, 0);         // prologue: k-block 0 into buf 0

        u32 buf = SOFF_BUF0;
        for (int kb = 0; kb < NKBLK; kb++) {
            const u32 nbuf = SOFF_BUF0 + (BUF_BYTES ^ (buf - SOFF_BUF0));  // other buffer
            if (kb + 1 < NKBLK) {
                stage(nbuf, t0, (kb + 1) * KBLK);   // prefetch next (overlaps compute below)
                CP_WAIT(1);
            } else {
                CP_WAIT(0);
            }
            __syncthreads();             // staged data of `buf` visible to all

            // ---- compute: 4 k16 steps on `buf` ----
            const u32 aBase = sb + buf + BUF_X + (u32)rowA * 128;
            const u32 wBase = sb + buf + wSel;
            #pragma unroll
            for (int ks = 0; ks < 4; ks++) {
                u32 ah[2][4];
                #pragma unroll
                for (int mt = 0; mt < 2; mt++) {
                    u32 c = (aC0 + (u32)ks * 32) ^ aXor;
                    ldsm_x4(ah[mt], aBase + (u32)mt * 2048 + c);
                }
                #pragma unroll
                for (int nt = 0; nt < 4; nt++) {
                    const int rowB = rowB0 + nt * 8;
                    const u32 boff = (u32)rowB * 128 + ((bC0 + (u32)ks * 32) ^ (((u32)(rowB & 7)) << 4));
                    u32 bh[2];
                    ldsm_x2(bh, wBase + boff);
                    #pragma unroll
                    for (int mt = 0; mt < 2; mt++)
                        mma16816(acc[mt][nt], ah[mt], bh);
                }
            }
            __syncthreads();             // compute on `buf` done before it is restaged
            buf = nbuf;
        }

        // ---- epilogue: activations at mma layout -> smem [64t][128o] ----
        // (GA/GB alias the staging buffers; trailing sync above ordered this)
        {
            float* dst = (float*)(smem + (gate ? SOFF_GB : SOFF_GA));
            #pragma unroll
            for (int mt = 0; mt < 2; mt++)
                #pragma unroll
                for (int nt = 0; nt < 4; nt++)
                    #pragma unroll
                    for (int e = 0; e < 4; e++) {
                        const int tl = tq * 32 + mt * 16 + (lane >> 2) + ((e >> 1) * 8);
                        const int oo = oq * 32 + nt * 8 + (lane & 3) * 2 + (e & 1);
                        const float tn = (float)(t0 + tl) * (1.0f / (float)T_TOTAL);
                        const float rt = 2.0f * sigf(fmaf(tn, biasR[oo], biasRB[oo]));
                        const float v  = acc[mt][nt][e];
                        dst[tl * 128 + oo] = gate ? (tanhf_(v + biasH[oo]) * rt)
                                                  : (sigf (v + biasG[oo]) * rt);
                    }
        }
        __syncthreads();

        // ---- scan: 4 quarter-spans of 16 t each, per o ----
        {
            const int oo = tid & 127, qt = tid >> 7;
            const float* GA = (const float*)(smem + SOFF_GA);
            const float* GB = (const float*)(smem + SOFF_GB);
            float A = 1.0f, Bv = 0.0f;
            #pragma unroll
            for (int i = 0; i < 16; i++) {
                const int tl = qt * 16 + i;
                const float a  = GA[tl * 128 + oo];
                const float bb = GB[tl * 128 + oo];
                Bv = fmaf(Bv, a, bb);
                A *= a;
            }
            qA[qt * 128 + oo] = A;
            qB[qt * 128 + oo] = Bv;
        }
        __syncthreads();

        if (tid < 128) {
            float As = stateA[tid], Bs = stateB[tid];
            #pragma unroll
            for (int qt = 0; qt < 4; qt++) {
                const float a  = qA[qt * 128 + tid];
                const float bb = qB[qt * 128 + tid];
                Bs = fmaf(Bs, a, bb);
                As *= a;
            }
            stateA[tid] = As;
            stateB[tid] = Bs;
        }
        // sync at top of next sub orders state/span reads vs restaging
    }

    __syncthreads();
    if (tid < 128) {
        const size_t idx = ((size_t)s * B_DIM + b) * OUT_DIM + o0 + tid;
        d_Aseg[idx] = stateA[tid];
        d_Bseg[idx] = stateB[tid];
    }
}

// ---------------- final combine over segments ----------------
__global__ void rnn_combine_kernel(float* __restrict__ out)
{
    const int idx = blockIdx.x * blockDim.x + threadIdx.x;
    float y = 0.0f;
    #pragma unroll
    for (int s = 0; s < NSEG; s++) {
        const float A = d_Aseg[s * B_DIM * OUT_DIM + idx];
        const float B = d_Bseg[s * B_DIM * OUT_DIM + idx];
        y = fmaf(y, A, B);
    }
    out[idx] = y;
}

extern "C" void kernel_launch(void* const* d_in, const int* in_sizes, int n_in,
                              void* d_out, int out_size)
{
    const float* x  = (const float*)d_in[0];
    const float* g  = (const float*)d_in[1];
    const float* gb = (const float*)d_in[2];
    const float* h  = (const float*)d_in[3];
    const float* hb = (const float*)d_in[4];
    const float* r  = (const float*)d_in[5];
    const float* rb = (const float*)d_in[6];
    float* out = (float*)d_out;

    cudaFuncSetAttribute(rnn_mma_kernel, cudaFuncAttributeMaxDynamicSharedMemorySize, SMEM_BYTES);

    dim3 pgrid(OUT_DIM / 32, INP_DIM / 32);
    wprep_kernel<<<pgrid, dim3(32, 32)>>>(g, h);
    dim3 grid(OUT_DIM / OTILE, B_DIM, NSEG);   // (4, 64, 8)
    rnn_mma_kernel<<<grid, 512, SMEM_BYTES>>>(x, gb, hb, r, rb);
    rnn_combine_kernel<<<(B_DIM * OUT_DIM) / 512, 512>>>(out);
}